// round 5
// baseline (speedup 1.0000x reference)
#include <cuda_runtime.h>
#include <cuda_bf16.h>
#include <math.h>

// Problem constants
#define B 4
#define S 2048
#define D 768
#define H 12
#define DK 64
#define M_ROWS (B * S)       // 8192
#define SCALE 0.125f         // 1/sqrt(64)

// -------- scratch (no allocations allowed) --------
__device__ float g_Q[M_ROWS * D];
__device__ float g_K[M_ROWS * D];
__device__ float g_V[M_ROWS * D];
__device__ float g_O[M_ROWS * D];

// ============================================================
// SGEMM: C[M=8192][N=768] = A[8192][768] @ B[768][768]^T + bias
// (both A and B are K-contiguous, "NT" GEMM)
// 128x128 block, BK=16, 256 threads, 8x8 per thread.
// Double-buffered smem with register staging of the next tile.
// ============================================================
__global__ __launch_bounds__(256) void gemm_nt_bias(
    const float* __restrict__ A,
    const float* __restrict__ Bm,
    const float* __restrict__ bias,
    float* __restrict__ C)
{
    __shared__ float As[2][16][132];
    __shared__ float Bs[2][16][132];

    const int t  = threadIdx.x;
    const int ty = t >> 4;      // 0..15
    const int tx = t & 15;      // 0..15
    const int rowBase = blockIdx.y * 128;
    const int colBase = blockIdx.x * 128;

    const float* Aptr = A  + (size_t)rowBase * D;
    const float* Bptr = Bm + (size_t)colBase * D;

    // load indices for the 128x16 tiles: 2 float4 per thread per matrix
    const int r_ld[2]  = { (t + 0)   >> 2, (t + 256) >> 2 };   // 0..127
    const int c4_ld[2] = { ((t + 0) & 3) << 2, ((t + 256) & 3) << 2 };

    float acc[8][8];
#pragma unroll
    for (int i = 0; i < 8; i++)
#pragma unroll
        for (int j = 0; j < 8; j++) acc[i][j] = 0.0f;

    // ---- prologue: load tile 0 into buffer 0 ----
#pragma unroll
    for (int l = 0; l < 2; l++) {
        float4 av = *(const float4*)(Aptr + (size_t)r_ld[l] * D + c4_ld[l]);
        As[0][c4_ld[l] + 0][r_ld[l]] = av.x; As[0][c4_ld[l] + 1][r_ld[l]] = av.y;
        As[0][c4_ld[l] + 2][r_ld[l]] = av.z; As[0][c4_ld[l] + 3][r_ld[l]] = av.w;
        float4 bv = *(const float4*)(Bptr + (size_t)r_ld[l] * D + c4_ld[l]);
        Bs[0][c4_ld[l] + 0][r_ld[l]] = bv.x; Bs[0][c4_ld[l] + 1][r_ld[l]] = bv.y;
        Bs[0][c4_ld[l] + 2][r_ld[l]] = bv.z; Bs[0][c4_ld[l] + 3][r_ld[l]] = bv.w;
    }
    __syncthreads();

    const int NT = D / 16;   // 48
    int buf = 0;

    for (int kt = 0; kt < NT; kt++) {
        // prefetch next tile into registers (overlaps with compute below)
        float4 av_n[2], bv_n[2];
        if (kt + 1 < NT) {
            int koff = (kt + 1) * 16;
#pragma unroll
            for (int l = 0; l < 2; l++) {
                av_n[l] = *(const float4*)(Aptr + (size_t)r_ld[l] * D + koff + c4_ld[l]);
                bv_n[l] = *(const float4*)(Bptr + (size_t)r_ld[l] * D + koff + c4_ld[l]);
            }
        }

        // compute from current buffer
#pragma unroll
        for (int k = 0; k < 16; k++) {
            float a[8], b[8];
            float4 a0 = *(const float4*)&As[buf][k][ty * 8];
            float4 a1 = *(const float4*)&As[buf][k][ty * 8 + 4];
            float4 b0 = *(const float4*)&Bs[buf][k][tx * 8];
            float4 b1 = *(const float4*)&Bs[buf][k][tx * 8 + 4];
            a[0]=a0.x; a[1]=a0.y; a[2]=a0.z; a[3]=a0.w;
            a[4]=a1.x; a[5]=a1.y; a[6]=a1.z; a[7]=a1.w;
            b[0]=b0.x; b[1]=b0.y; b[2]=b0.z; b[3]=b0.w;
            b[4]=b1.x; b[5]=b1.y; b[6]=b1.z; b[7]=b1.w;
#pragma unroll
            for (int i = 0; i < 8; i++)
#pragma unroll
                for (int j = 0; j < 8; j++)
                    acc[i][j] = fmaf(a[i], b[j], acc[i][j]);
        }

        // store prefetched tile into the other buffer
        if (kt + 1 < NT) {
            int nb = buf ^ 1;
            __syncthreads();
#pragma unroll
            for (int l = 0; l < 2; l++) {
                As[nb][c4_ld[l] + 0][r_ld[l]] = av_n[l].x;
                As[nb][c4_ld[l] + 1][r_ld[l]] = av_n[l].y;
                As[nb][c4_ld[l] + 2][r_ld[l]] = av_n[l].z;
                As[nb][c4_ld[l] + 3][r_ld[l]] = av_n[l].w;
                Bs[nb][c4_ld[l] + 0][r_ld[l]] = bv_n[l].x;
                Bs[nb][c4_ld[l] + 1][r_ld[l]] = bv_n[l].y;
                Bs[nb][c4_ld[l] + 2][r_ld[l]] = bv_n[l].z;
                Bs[nb][c4_ld[l] + 3][r_ld[l]] = bv_n[l].w;
            }
            __syncthreads();
            buf = nb;
        }
    }

    // epilogue: +bias, write
#pragma unroll
    for (int i = 0; i < 8; i++) {
        int row = rowBase + ty * 8 + i;
        float* Crow = C + (size_t)row * D + colBase + tx * 8;
        const float* brow = bias + colBase + tx * 8;
#pragma unroll
        for (int j4 = 0; j4 < 8; j4 += 4) {
            float4 v;
            v.x = acc[i][j4 + 0] + brow[j4 + 0];
            v.y = acc[i][j4 + 1] + brow[j4 + 1];
            v.z = acc[i][j4 + 2] + brow[j4 + 2];
            v.w = acc[i][j4 + 3] + brow[j4 + 3];
            *(float4*)(Crow + j4) = v;
        }
    }
}

// ============================================================
// Flash attention (causal), fp32.
// Grid: (32 q-tiles, 48 batch*head). Block: 256 threads.
// Q tile = 64 rows, KV tile = 64 rows, dk = 64.
// Thread (ty,tx) in 16x16 grid owns 4x4 micro-tiles.
// ============================================================
#define ATT_PAD 68
#define SMEM_ATTN (4 * 64 * ATT_PAD * 4)

__global__ __launch_bounds__(256) void flash_attn(
    const float* __restrict__ Q,
    const float* __restrict__ K,
    const float* __restrict__ V,
    float* __restrict__ O)
{
    extern __shared__ float smem[];
    float* Qs = smem;                    // [64][ATT_PAD]
    float* Ks = Qs + 64 * ATT_PAD;
    float* Vs = Ks + 64 * ATT_PAD;
    float* Ps = Vs + 64 * ATT_PAD;

    const int t  = threadIdx.x;
    const int ty = t >> 4;       // 0..15
    const int tx = t & 15;       // 0..15
    const int qb = blockIdx.x;   // 0..31
    const int bh = blockIdx.y;   // 0..47
    const int bb = bh / H;
    const int hh = bh % H;

    const float* Qbase = Q + ((size_t)bb * S) * D + hh * DK;
    const float* Kbase = K + ((size_t)bb * S) * D + hh * DK;
    const float* Vbase = V + ((size_t)bb * S) * D + hh * DK;
    float*       Obase = O + ((size_t)bb * S) * D + hh * DK;

    // ---- load Q tile (scaled) ----
#pragma unroll
    for (int l = 0; l < 4; l++) {
        int idx = t + l * 256;        // float4 units
        int r   = idx >> 4;           // 0..63
        int c4  = (idx & 15) << 2;    // 0..60
        float4 v = *(const float4*)(Qbase + (size_t)(qb * 64 + r) * D + c4);
        v.x *= SCALE; v.y *= SCALE; v.z *= SCALE; v.w *= SCALE;
        *(float4*)&Qs[r * ATT_PAD + c4] = v;
    }

    const int r0 = ty * 4;
    const int c0 = tx * 4;
    const int d0 = tx * 4;

    float m_i[4], l_i[4], o[4][4];
#pragma unroll
    for (int i = 0; i < 4; i++) {
        m_i[i] = -INFINITY; l_i[i] = 0.0f;
#pragma unroll
        for (int j = 0; j < 4; j++) o[i][j] = 0.0f;
    }

    for (int kt = 0; kt <= qb; kt++) {
        __syncthreads();   // protect Ks/Vs/Ps from previous iteration
#pragma unroll
        for (int l = 0; l < 4; l++) {
            int idx = t + l * 256;
            int r   = idx >> 4;
            int c4  = (idx & 15) << 2;
            *(float4*)&Ks[r * ATT_PAD + c4] =
                *(const float4*)(Kbase + (size_t)(kt * 64 + r) * D + c4);
            *(float4*)&Vs[r * ATT_PAD + c4] =
                *(const float4*)(Vbase + (size_t)(kt * 64 + r) * D + c4);
        }
        __syncthreads();

        // S = Qs @ Ks^T  (4x4 per thread)
        float s[4][4];
#pragma unroll
        for (int i = 0; i < 4; i++)
#pragma unroll
            for (int j = 0; j < 4; j++) s[i][j] = 0.0f;

#pragma unroll 8
        for (int d = 0; d < 64; d++) {
            float a[4], b[4];
#pragma unroll
            for (int i = 0; i < 4; i++) a[i] = Qs[(r0 + i) * ATT_PAD + d];
#pragma unroll
            for (int j = 0; j < 4; j++) b[j] = Ks[(c0 + j) * ATT_PAD + d];
#pragma unroll
            for (int i = 0; i < 4; i++)
#pragma unroll
                for (int j = 0; j < 4; j++)
                    s[i][j] = fmaf(a[i], b[j], s[i][j]);
        }

        // causal mask on diagonal tile
        if (kt == qb) {
#pragma unroll
            for (int i = 0; i < 4; i++) {
                int qr = qb * 64 + r0 + i;
#pragma unroll
                for (int j = 0; j < 4; j++) {
                    int kc = kt * 64 + c0 + j;
                    if (kc > qr) s[i][j] = -1e30f;
                }
            }
        }

        // online softmax: per-row max across 64 cols (16 tx threads)
#pragma unroll
        for (int i = 0; i < 4; i++) {
            float mx = s[i][0];
#pragma unroll
            for (int j = 1; j < 4; j++) mx = fmaxf(mx, s[i][j]);
#pragma unroll
            for (int off = 8; off >= 1; off >>= 1)
                mx = fmaxf(mx, __shfl_xor_sync(0xffffffffu, mx, off));

            float m_new = fmaxf(m_i[i], mx);
            float f = __expf(m_i[i] - m_new);
            m_i[i] = m_new;

            float rs = 0.0f;
#pragma unroll
            for (int j = 0; j < 4; j++) {
                float p = __expf(s[i][j] - m_new);
                s[i][j] = p;
                rs += p;
            }
#pragma unroll
            for (int off = 8; off >= 1; off >>= 1)
                rs += __shfl_xor_sync(0xffffffffu, rs, off);

            l_i[i] = l_i[i] * f + rs;
#pragma unroll
            for (int j = 0; j < 4; j++) o[i][j] *= f;
        }

        // store P to smem
#pragma unroll
        for (int i = 0; i < 4; i++) {
            float4 v; v.x = s[i][0]; v.y = s[i][1]; v.z = s[i][2]; v.w = s[i][3];
            *(float4*)&Ps[(r0 + i) * ATT_PAD + c0] = v;
        }
        __syncthreads();

        // O += P @ V  (4x4 per thread over 64 c)
#pragma unroll 8
        for (int c = 0; c < 64; c++) {
            float a[4];
#pragma unroll
            for (int i = 0; i < 4; i++) a[i] = Ps[(r0 + i) * ATT_PAD + c];
            float4 bv = *(const float4*)&Vs[c * ATT_PAD + d0];
            float b[4] = {bv.x, bv.y, bv.z, bv.w};
#pragma unroll
            for (int i = 0; i < 4; i++)
#pragma unroll
                for (int j = 0; j < 4; j++)
                    o[i][j] = fmaf(a[i], b[j], o[i][j]);
        }
    }

    // finalize + write
#pragma unroll
    for (int i = 0; i < 4; i++) {
        float inv = 1.0f / l_i[i];
        float4 v;
        v.x = o[i][0] * inv; v.y = o[i][1] * inv;
        v.z = o[i][2] * inv; v.w = o[i][3] * inv;
        *(float4*)(Obase + (size_t)(qb * 64 + r0 + i) * D + d0) = v;
    }
}

// ============================================================
extern "C" void kernel_launch(void* const* d_in, const int* in_sizes, int n_in,
                              void* d_out, int out_size)
{
    const float* x   = (const float*)d_in[0];
    const float* w_q = (const float*)d_in[1];
    const float* b_q = (const float*)d_in[2];
    const float* w_k = (const float*)d_in[3];
    const float* b_k = (const float*)d_in[4];
    const float* w_v = (const float*)d_in[5];
    const float* b_v = (const float*)d_in[6];
    const float* w_o = (const float*)d_in[7];
    const float* b_o = (const float*)d_in[8];

    float *Qb, *Kb, *Vb, *Ob;
    cudaGetSymbolAddress((void**)&Qb, g_Q);
    cudaGetSymbolAddress((void**)&Kb, g_K);
    cudaGetSymbolAddress((void**)&Vb, g_V);
    cudaGetSymbolAddress((void**)&Ob, g_O);

    dim3 ggrid(D / 128, M_ROWS / 128);   // (6, 64)
    gemm_nt_bias<<<ggrid, 256>>>(x, w_q, b_q, Qb);
    gemm_nt_bias<<<ggrid, 256>>>(x, w_k, b_k, Kb);
    gemm_nt_bias<<<ggrid, 256>>>(x, w_v, b_v, Vb);

    cudaFuncSetAttribute(flash_attn, cudaFuncAttributeMaxDynamicSharedMemorySize,
                         SMEM_ATTN);
    flash_attn<<<dim3(S / 64, B * H), 256, SMEM_ATTN>>>(Qb, Kb, Vb, Ob);

    gemm_nt_bias<<<ggrid, 256>>>(Ob, w_o, b_o, (float*)d_out);
}

// round 11
// speedup vs baseline: 1.6995x; 1.6995x over previous
#include <cuda_runtime.h>
#include <cuda_bf16.h>
#include <math.h>
#include <stdint.h>

// Problem constants
#define B 4
#define S 2048
#define D 768
#define H 12
#define DK 64
#define M_ROWS (B * S)       // 8192
#define SCALE 0.125f         // 1/sqrt(64)

// -------- scratch (no allocations allowed) --------
__device__ float g_Q[M_ROWS * D];
__device__ float g_K[M_ROWS * D];
__device__ float g_V[M_ROWS * D];
__device__ float g_O[M_ROWS * D];
__device__ __nv_bfloat16 g_xh[M_ROWS * D];
__device__ __nv_bfloat16 g_xl[M_ROWS * D];
__device__ __nv_bfloat16 g_oh[M_ROWS * D];
__device__ __nv_bfloat16 g_ol[M_ROWS * D];
__device__ __nv_bfloat16 g_wh[4 * D * D];
__device__ __nv_bfloat16 g_wl[4 * D * D];

__device__ __forceinline__ uint32_t smem_u32(const void* p) {
    uint32_t a;
    asm("{ .reg .u64 t; cvta.to.shared.u64 t, %1; cvt.u32.u64 %0, t; }"
        : "=r"(a) : "l"(p));
    return a;
}

// ============================================================
// Split conversion: fp32 -> (bf16 hi, bf16 lo), 4 elems/thread
// ============================================================
__global__ void convert_split(const float4* __restrict__ in,
                              __nv_bfloat162* __restrict__ hi,
                              __nv_bfloat162* __restrict__ lo, int n4)
{
    int i = blockIdx.x * blockDim.x + threadIdx.x;
    if (i >= n4) return;
    float4 v = in[i];
    __nv_bfloat16 h0 = __float2bfloat16(v.x);
    __nv_bfloat16 h1 = __float2bfloat16(v.y);
    __nv_bfloat16 h2 = __float2bfloat16(v.z);
    __nv_bfloat16 h3 = __float2bfloat16(v.w);
    __nv_bfloat16 l0 = __float2bfloat16(v.x - __bfloat162float(h0));
    __nv_bfloat16 l1 = __float2bfloat16(v.y - __bfloat162float(h1));
    __nv_bfloat16 l2 = __float2bfloat16(v.z - __bfloat162float(h2));
    __nv_bfloat16 l3 = __float2bfloat16(v.w - __bfloat162float(h3));
    __nv_bfloat162 a, b, c, d;
    a.x = h0; a.y = h1; b.x = h2; b.y = h3;
    c.x = l0; c.y = l1; d.x = l2; d.y = l3;
    hi[2 * i] = a; hi[2 * i + 1] = b;
    lo[2 * i] = c; lo[2 * i + 1] = d;
}

// ============================================================
// bf16x3 GEMM via mma.sync (m16n8k16):
//   C[8192][768] = Ah*Bh^T + Al*Bh^T + Ah*Bl^T + bias
// CTA 128x64, BK=32, 256 threads (8 warps as 4x2).
// Warp tile 32x32: 2 m-frags x 4 n-frags, fp32 acc in regs.
// ============================================================
#define GPAD 40   // bf16 per smem row (32 data + 8 pad); 80B row stride

__device__ __forceinline__ void ldmx4(uint32_t* r, uint32_t addr) {
    asm volatile("ldmatrix.sync.aligned.m8n8.x4.shared.b16 {%0,%1,%2,%3}, [%4];"
        : "=r"(r[0]), "=r"(r[1]), "=r"(r[2]), "=r"(r[3]) : "r"(addr));
}

__device__ __forceinline__ void mma_bf16(float* c,
    const uint32_t* a, const uint32_t* b)
{
    asm volatile(
        "mma.sync.aligned.m16n8k16.row.col.f32.bf16.bf16.f32 "
        "{%0,%1,%2,%3}, {%4,%5,%6,%7}, {%8,%9}, {%0,%1,%2,%3};"
        : "+f"(c[0]), "+f"(c[1]), "+f"(c[2]), "+f"(c[3])
        : "r"(a[0]), "r"(a[1]), "r"(a[2]), "r"(a[3]), "r"(b[0]), "r"(b[1]));
}

__global__ __launch_bounds__(256) void gemm_mma(
    const __nv_bfloat16* __restrict__ Ah, const __nv_bfloat16* __restrict__ Al,
    const __nv_bfloat16* __restrict__ Bh, const __nv_bfloat16* __restrict__ Bl,
    const float* __restrict__ bias, float* __restrict__ C)
{
    __shared__ __nv_bfloat16 sAh[128][GPAD];
    __shared__ __nv_bfloat16 sAl[128][GPAD];
    __shared__ __nv_bfloat16 sBh[64][GPAD];
    __shared__ __nv_bfloat16 sBl[64][GPAD];

    const int t = threadIdx.x;
    const int lane = t & 31;
    const int wid = t >> 5;
    const int warp_m = wid & 3;      // 0..3 -> 32 rows each
    const int warp_n = wid >> 2;     // 0..1 -> 32 cols each
    const int m0 = blockIdx.y * 128;
    const int n0 = blockIdx.x * 64;

    const uint32_t uAh = smem_u32(&sAh[0][0]);
    const uint32_t uAl = smem_u32(&sAl[0][0]);
    const uint32_t uBh = smem_u32(&sBh[0][0]);
    const uint32_t uBl = smem_u32(&sBl[0][0]);

    float acc[2][4][4];
#pragma unroll
    for (int mi = 0; mi < 2; mi++)
#pragma unroll
        for (int ni = 0; ni < 4; ni++)
#pragma unroll
            for (int q = 0; q < 4; q++) acc[mi][ni][q] = 0.0f;

    // ldmatrix source addresses (per k16 step base)
    const int lrow = lane & 15;
    const int lcol = (lane >> 4) << 3;   // 0 or 8

    for (int kt = 0; kt < D; kt += 32) {
        __syncthreads();
        // load A tiles: 128 rows x 4 chunks(16B) = 512 chunks; 2/thread
#pragma unroll
        for (int l = 0; l < 2; l++) {
            int idx = t + l * 256;
            int r = idx >> 2, c = idx & 3;
            const size_t g = (size_t)(m0 + r) * D + kt + c * 8;
            *(float4*)&sAh[r][c * 8] = *(const float4*)(Ah + g);
            *(float4*)&sAl[r][c * 8] = *(const float4*)(Al + g);
        }
        // B tiles: 64 rows x 4 chunks = 256 chunks; 1/thread
        {
            int r = t >> 2, c = t & 3;
            const size_t g = (size_t)(n0 + r) * D + kt + c * 8;
            *(float4*)&sBh[r][c * 8] = *(const float4*)(Bh + g);
            *(float4*)&sBl[r][c * 8] = *(const float4*)(Bl + g);
        }
        __syncthreads();

#pragma unroll
        for (int ks = 0; ks < 2; ks++) {
            const int kc = ks * 16 + lcol;
            uint32_t ah[2][4], al[2][4], bh[4][2], bl[4][2];
#pragma unroll
            for (int mi = 0; mi < 2; mi++) {
                int r = warp_m * 32 + mi * 16 + lrow;
                ldmx4(ah[mi], uAh + (uint32_t)(r * GPAD + kc) * 2);
                ldmx4(al[mi], uAl + (uint32_t)(r * GPAD + kc) * 2);
            }
#pragma unroll
            for (int np = 0; np < 2; np++) {
                int r = warp_n * 32 + np * 16 + lrow;
                uint32_t tmp[4];
                ldmx4(tmp, uBh + (uint32_t)(r * GPAD + kc) * 2);
                bh[np * 2 + 0][0] = tmp[0]; bh[np * 2 + 0][1] = tmp[2];
                bh[np * 2 + 1][0] = tmp[1]; bh[np * 2 + 1][1] = tmp[3];
                ldmx4(tmp, uBl + (uint32_t)(r * GPAD + kc) * 2);
                bl[np * 2 + 0][0] = tmp[0]; bl[np * 2 + 0][1] = tmp[2];
                bl[np * 2 + 1][0] = tmp[1]; bl[np * 2 + 1][1] = tmp[3];
            }
#pragma unroll
            for (int mi = 0; mi < 2; mi++)
#pragma unroll
                for (int ni = 0; ni < 4; ni++) {
                    mma_bf16(acc[mi][ni], ah[mi], bh[ni]);
                    mma_bf16(acc[mi][ni], al[mi], bh[ni]);
                    mma_bf16(acc[mi][ni], ah[mi], bl[ni]);
                }
        }
    }

    // epilogue: C frag layout: {c0,c1} at (row=lane/4, col=(lane%4)*2),
    // {c2,c3} at row+8.
    const int rb = m0 + warp_m * 32 + (lane >> 2);
    const int cb = n0 + warp_n * 32 + (lane & 3) * 2;
#pragma unroll
    for (int mi = 0; mi < 2; mi++)
#pragma unroll
        for (int ni = 0; ni < 4; ni++) {
            int r = rb + mi * 16;
            int c = cb + ni * 8;
            float2 v0, v1;
            v0.x = acc[mi][ni][0] + bias[c];
            v0.y = acc[mi][ni][1] + bias[c + 1];
            v1.x = acc[mi][ni][2] + bias[c];
            v1.y = acc[mi][ni][3] + bias[c + 1];
            *(float2*)(C + (size_t)r * D + c) = v0;
            *(float2*)(C + (size_t)(r + 8) * D + c) = v1;
        }
}

// ============================================================
// Flash attention (causal), fp32 — R5 kernel with bank-conflict
// fix: thread's S-columns are {tx + 16*j}; Ks pad 66 (lane stride
// 66 -> 16 distinct banks), Ps pad 66.
// ============================================================
#define QPAD 68
#define KPAD 66
#define VPAD 68
#define PPAD 66
#define SMEM_ATTN ((64 * QPAD + 64 * KPAD + 64 * VPAD + 64 * PPAD) * 4)

__global__ __launch_bounds__(256) void flash_attn(
    const float* __restrict__ Q,
    const float* __restrict__ K,
    const float* __restrict__ V,
    float* __restrict__ O)
{
    extern __shared__ float fsmem[];
    float* Qs = fsmem;                       // [64][QPAD]
    float* Ks = Qs + 64 * QPAD;              // [64][KPAD]
    float* Vs = Ks + 64 * KPAD;              // [64][VPAD]
    float* Ps = Vs + 64 * VPAD;              // [64][PPAD]

    const int t  = threadIdx.x;
    const int ty = t >> 4;
    const int tx = t & 15;
    const int qb = blockIdx.x;
    const int bh = blockIdx.y;
    const int bb = bh / H;
    const int hh = bh % H;

    const float* Qbase = Q + ((size_t)bb * S) * D + hh * DK;
    const float* Kbase = K + ((size_t)bb * S) * D + hh * DK;
    const float* Vbase = V + ((size_t)bb * S) * D + hh * DK;
    float*       Obase = O + ((size_t)bb * S) * D + hh * DK;

#pragma unroll
    for (int l = 0; l < 4; l++) {
        int idx = t + l * 256;
        int r   = idx >> 4;
        int c4  = (idx & 15) << 2;
        float4 v = *(const float4*)(Qbase + (size_t)(qb * 64 + r) * D + c4);
        v.x *= SCALE; v.y *= SCALE; v.z *= SCALE; v.w *= SCALE;
        *(float4*)&Qs[r * QPAD + c4] = v;
    }

    const int r0 = ty * 4;
    const int d0 = tx * 4;

    float m_i[4], l_i[4], o[4][4];
#pragma unroll
    for (int i = 0; i < 4; i++) {
        m_i[i] = -INFINITY; l_i[i] = 0.0f;
#pragma unroll
        for (int j = 0; j < 4; j++) o[i][j] = 0.0f;
    }

    for (int kt = 0; kt <= qb; kt++) {
        __syncthreads();
#pragma unroll
        for (int l = 0; l < 4; l++) {
            int idx = t + l * 256;
            int r   = idx >> 4;
            int c4  = (idx & 15) << 2;
            float4 kv = *(const float4*)(Kbase + (size_t)(kt * 64 + r) * D + c4);
            Ks[r * KPAD + c4 + 0] = kv.x;
            Ks[r * KPAD + c4 + 1] = kv.y;
            Ks[r * KPAD + c4 + 2] = kv.z;
            Ks[r * KPAD + c4 + 3] = kv.w;
            *(float4*)&Vs[r * VPAD + c4] =
                *(const float4*)(Vbase + (size_t)(kt * 64 + r) * D + c4);
        }
        __syncthreads();

        // S = Qs @ Ks^T; thread's cols = {tx + 16*j}
        float s[4][4];
#pragma unroll
        for (int i = 0; i < 4; i++)
#pragma unroll
            for (int j = 0; j < 4; j++) s[i][j] = 0.0f;

#pragma unroll 8
        for (int d = 0; d < 64; d++) {
            float a[4], b[4];
#pragma unroll
            for (int i = 0; i < 4; i++) a[i] = Qs[(r0 + i) * QPAD + d];
#pragma unroll
            for (int j = 0; j < 4; j++) b[j] = Ks[(tx + 16 * j) * KPAD + d];
#pragma unroll
            for (int i = 0; i < 4; i++)
#pragma unroll
                for (int j = 0; j < 4; j++)
                    s[i][j] = fmaf(a[i], b[j], s[i][j]);
        }

        // causal mask on diagonal tile
        if (kt == qb) {
#pragma unroll
            for (int i = 0; i < 4; i++) {
                int qr = qb * 64 + r0 + i;
#pragma unroll
                for (int j = 0; j < 4; j++) {
                    int kc = kt * 64 + tx + 16 * j;
                    if (kc > qr) s[i][j] = -1e30f;
                }
            }
        }

        // online softmax across the 16 tx lanes
#pragma unroll
        for (int i = 0; i < 4; i++) {
            float mx = s[i][0];
#pragma unroll
            for (int j = 1; j < 4; j++) mx = fmaxf(mx, s[i][j]);
#pragma unroll
            for (int off = 8; off >= 1; off >>= 1)
                mx = fmaxf(mx, __shfl_xor_sync(0xffffffffu, mx, off));

            float m_new = fmaxf(m_i[i], mx);
            float f = __expf(m_i[i] - m_new);
            m_i[i] = m_new;

            float rs = 0.0f;
#pragma unroll
            for (int j = 0; j < 4; j++) {
                float p = __expf(s[i][j] - m_new);
                s[i][j] = p;
                rs += p;
            }
#pragma unroll
            for (int off = 8; off >= 1; off >>= 1)
                rs += __shfl_xor_sync(0xffffffffu, rs, off);

            l_i[i] = l_i[i] * f + rs;
#pragma unroll
            for (int j = 0; j < 4; j++) o[i][j] *= f;
        }

        // store P (scattered cols, conflict-free: lane stride 1)
#pragma unroll
        for (int i = 0; i < 4; i++)
#pragma unroll
            for (int j = 0; j < 4; j++)
                Ps[(r0 + i) * PPAD + tx + 16 * j] = s[i][j];
        __syncthreads();

        // O += P @ V
#pragma unroll 8
        for (int c = 0; c < 64; c++) {
            float a[4];
#pragma unroll
            for (int i = 0; i < 4; i++) a[i] = Ps[(r0 + i) * PPAD + c];
            float4 bv = *(const float4*)&Vs[c * VPAD + d0];
            float b[4] = {bv.x, bv.y, bv.z, bv.w};
#pragma unroll
            for (int i = 0; i < 4; i++)
#pragma unroll
                for (int j = 0; j < 4; j++)
                    o[i][j] = fmaf(a[i], b[j], o[i][j]);
        }
    }

#pragma unroll
    for (int i = 0; i < 4; i++) {
        float inv = 1.0f / l_i[i];
        float4 v;
        v.x = o[i][0] * inv; v.y = o[i][1] * inv;
        v.z = o[i][2] * inv; v.w = o[i][3] * inv;
        *(float4*)(Obase + (size_t)(qb * 64 + r0 + i) * D + d0) = v;
    }
}

// ============================================================
extern "C" void kernel_launch(void* const* d_in, const int* in_sizes, int n_in,
                              void* d_out, int out_size)
{
    const float* x   = (const float*)d_in[0];
    const float* w_q = (const float*)d_in[1];
    const float* b_q = (const float*)d_in[2];
    const float* w_k = (const float*)d_in[3];
    const float* b_k = (const float*)d_in[4];
    const float* w_v = (const float*)d_in[5];
    const float* b_v = (const float*)d_in[6];
    const float* w_o = (const float*)d_in[7];
    const float* b_o = (const float*)d_in[8];

    float *Qb, *Kb, *Vb, *Ob;
    __nv_bfloat16 *xh, *xl, *oh, *ol, *wh, *wl;
    cudaGetSymbolAddress((void**)&Qb, g_Q);
    cudaGetSymbolAddress((void**)&Kb, g_K);
    cudaGetSymbolAddress((void**)&Vb, g_V);
    cudaGetSymbolAddress((void**)&Ob, g_O);
    cudaGetSymbolAddress((void**)&xh, g_xh);
    cudaGetSymbolAddress((void**)&xl, g_xl);
    cudaGetSymbolAddress((void**)&oh, g_oh);
    cudaGetSymbolAddress((void**)&ol, g_ol);
    cudaGetSymbolAddress((void**)&wh, g_wh);
    cudaGetSymbolAddress((void**)&wl, g_wl);

    cudaFuncSetAttribute(flash_attn,
        cudaFuncAttributeMaxDynamicSharedMemorySize, SMEM_ATTN);

    // split conversions
    {
        int n4 = M_ROWS * D / 4;
        convert_split<<<(n4 + 255) / 256, 256>>>(
            (const float4*)x, (__nv_bfloat162*)xh, (__nv_bfloat162*)xl, n4);
        int w4 = D * D / 4;
        const float* ws[4] = {w_q, w_k, w_v, w_o};
        for (int i = 0; i < 4; i++) {
            convert_split<<<(w4 + 255) / 256, 256>>>(
                (const float4*)ws[i],
                (__nv_bfloat162*)(wh + (size_t)i * D * D),
                (__nv_bfloat162*)(wl + (size_t)i * D * D), w4);
        }
    }

    dim3 ggrid(D / 64, M_ROWS / 128);   // (12, 64)
    gemm_mma<<<ggrid, 256>>>(xh, xl, wh + 0 * (size_t)D * D,
                             wl + 0 * (size_t)D * D, b_q, Qb);
    gemm_mma<<<ggrid, 256>>>(xh, xl, wh + 1 * (size_t)D * D,
                             wl + 1 * (size_t)D * D, b_k, Kb);
    gemm_mma<<<ggrid, 256>>>(xh, xl, wh + 2 * (size_t)D * D,
                             wl + 2 * (size_t)D * D, b_v, Vb);

    flash_attn<<<dim3(S / 64, B * H), 256, SMEM_ATTN>>>(Qb, Kb, Vb, Ob);

    {
        int n4 = M_ROWS * D / 4;
        convert_split<<<(n4 + 255) / 256, 256>>>(
            (const float4*)Ob, (__nv_bfloat162*)oh, (__nv_bfloat162*)ol, n4);
    }
    gemm_mma<<<ggrid, 256>>>(oh, ol, wh + 3 * (size_t)D * D,
                             wl + 3 * (size_t)D * D, b_o, (float*)d_out);
}

// round 16
// speedup vs baseline: 2.6399x; 1.5534x over previous
#include <cuda_runtime.h>
#include <cuda_bf16.h>
#include <math.h>
#include <stdint.h>

// Problem constants
#define B 4
#define S 2048
#define D 768
#define H 12
#define DK 64
#define M_ROWS (B * S)       // 8192
#define SCALE 0.125f         // 1/sqrt(64)

// -------- scratch (no allocations allowed) --------
__device__ float g_Q[M_ROWS * D];
__device__ float g_K[M_ROWS * D];
__device__ float g_V[M_ROWS * D];
__device__ __nv_bfloat16 g_xh[M_ROWS * D];
__device__ __nv_bfloat16 g_xl[M_ROWS * D];
__device__ __nv_bfloat16 g_oh[M_ROWS * D];
__device__ __nv_bfloat16 g_ol[M_ROWS * D];
__device__ __nv_bfloat16 g_wh[4 * D * D];
__device__ __nv_bfloat16 g_wl[4 * D * D];
__device__ __nv_bfloat16 g_qh[M_ROWS * D];
__device__ __nv_bfloat16 g_ql[M_ROWS * D];
__device__ __nv_bfloat16 g_kh[M_ROWS * D];
__device__ __nv_bfloat16 g_kl[M_ROWS * D];
__device__ __nv_bfloat16 g_vth[B * H * DK * S];
__device__ __nv_bfloat16 g_vtl[B * H * DK * S];

__device__ __forceinline__ uint32_t smem_u32(const void* p) {
    uint32_t a;
    asm("{ .reg .u64 t; cvta.to.shared.u64 t, %1; cvt.u32.u64 %0, t; }"
        : "=r"(a) : "l"(p));
    return a;
}

__device__ __forceinline__ void ldmx4(uint32_t* r, uint32_t addr) {
    asm volatile("ldmatrix.sync.aligned.m8n8.x4.shared.b16 {%0,%1,%2,%3}, [%4];"
        : "=r"(r[0]), "=r"(r[1]), "=r"(r[2]), "=r"(r[3]) : "r"(addr));
}
__device__ __forceinline__ void ldmx2(uint32_t* r, uint32_t addr) {
    asm volatile("ldmatrix.sync.aligned.m8n8.x2.shared.b16 {%0,%1}, [%2];"
        : "=r"(r[0]), "=r"(r[1]) : "r"(addr));
}
__device__ __forceinline__ void mma_bf16(float* c,
    const uint32_t* a, const uint32_t* b)
{
    asm volatile(
        "mma.sync.aligned.m16n8k16.row.col.f32.bf16.bf16.f32 "
        "{%0,%1,%2,%3}, {%4,%5,%6,%7}, {%8,%9}, {%0,%1,%2,%3};"
        : "+f"(c[0]), "+f"(c[1]), "+f"(c[2]), "+f"(c[3])
        : "r"(a[0]), "r"(a[1]), "r"(a[2]), "r"(a[3]), "r"(b[0]), "r"(b[1]));
}

__device__ __forceinline__ void split_pack(float a, float b,
                                           uint32_t& hi, uint32_t& lo)
{
    __nv_bfloat16 ha = __float2bfloat16(a), hb = __float2bfloat16(b);
    __nv_bfloat162 Hv, Lv;
    Hv.x = ha; Hv.y = hb;
    Lv.x = __float2bfloat16(a - __bfloat162float(ha));
    Lv.y = __float2bfloat16(b - __bfloat162float(hb));
    hi = *(uint32_t*)&Hv; lo = *(uint32_t*)&Lv;
}

// ============================================================
// Split conversion: fp32 -> (bf16 hi, bf16 lo), scaled.
// ============================================================
__global__ void convert_split(const float4* __restrict__ in,
                              __nv_bfloat162* __restrict__ hi,
                              __nv_bfloat162* __restrict__ lo,
                              int n4, float scale)
{
    int i = blockIdx.x * blockDim.x + threadIdx.x;
    if (i >= n4) return;
    float4 v = in[i];
    v.x *= scale; v.y *= scale; v.z *= scale; v.w *= scale;
    uint32_t h0, l0, h1, l1;
    split_pack(v.x, v.y, h0, l0);
    split_pack(v.z, v.w, h1, l1);
    ((uint32_t*)hi)[2 * i] = h0; ((uint32_t*)hi)[2 * i + 1] = h1;
    ((uint32_t*)lo)[2 * i] = l0; ((uint32_t*)lo)[2 * i + 1] = l1;
}

// ============================================================
// V transpose + split: g_V [b*S][768] fp32 ->
//   g_vth/g_vtl [b*H + h][dk=64][S] bf16
// Block: 64 seq x 64 dk tile for one (b,h). 256 threads.
// ============================================================
__global__ __launch_bounds__(256) void transpose_split_v(
    const float* __restrict__ V,
    __nv_bfloat16* __restrict__ vth, __nv_bfloat16* __restrict__ vtl)
{
    __shared__ float tile[64][65];
    const int sblk = blockIdx.x;     // 0..31
    const int bh = blockIdx.y;       // 0..47
    const int bb = bh / H, hh = bh % H;
    const int t = threadIdx.x;

#pragma unroll
    for (int l = 0; l < 4; l++) {
        int idx = t + l * 256;
        int r = idx >> 4, c4 = (idx & 15) << 2;
        float4 v = *(const float4*)(V +
            ((size_t)bb * S + sblk * 64 + r) * D + hh * 64 + c4);
        tile[r][c4 + 0] = v.x; tile[r][c4 + 1] = v.y;
        tile[r][c4 + 2] = v.z; tile[r][c4 + 3] = v.w;
    }
    __syncthreads();

#pragma unroll
    for (int l = 0; l < 8; l++) {
        int p = t + l * 256;         // 0..2047
        int c = p >> 5;              // dk 0..63
        int sp = p & 31;             // seq pair
        float v0 = tile[2 * sp][c], v1 = tile[2 * sp + 1][c];
        uint32_t h, lo;
        split_pack(v0, v1, h, lo);
        size_t addr = ((size_t)bh * 64 + c) * S + sblk * 64 + 2 * sp;
        *(uint32_t*)(vth + addr) = h;
        *(uint32_t*)(vtl + addr) = lo;
    }
}

// ============================================================
// bf16x3 GEMM via mma.sync (m16n8k16)  — unchanged (passing R11)
// ============================================================
#define GPAD 40

__global__ __launch_bounds__(256) void gemm_mma(
    const __nv_bfloat16* __restrict__ Ah, const __nv_bfloat16* __restrict__ Al,
    const __nv_bfloat16* __restrict__ Bh, const __nv_bfloat16* __restrict__ Bl,
    const float* __restrict__ bias, float* __restrict__ C)
{
    __shared__ __nv_bfloat16 sAh[128][GPAD];
    __shared__ __nv_bfloat16 sAl[128][GPAD];
    __shared__ __nv_bfloat16 sBh[64][GPAD];
    __shared__ __nv_bfloat16 sBl[64][GPAD];

    const int t = threadIdx.x;
    const int lane = t & 31;
    const int wid = t >> 5;
    const int warp_m = wid & 3;
    const int warp_n = wid >> 2;
    const int m0 = blockIdx.y * 128;
    const int n0 = blockIdx.x * 64;

    const uint32_t uAh = smem_u32(&sAh[0][0]);
    const uint32_t uAl = smem_u32(&sAl[0][0]);
    const uint32_t uBh = smem_u32(&sBh[0][0]);
    const uint32_t uBl = smem_u32(&sBl[0][0]);

    float acc[2][4][4];
#pragma unroll
    for (int mi = 0; mi < 2; mi++)
#pragma unroll
        for (int ni = 0; ni < 4; ni++)
#pragma unroll
            for (int q = 0; q < 4; q++) acc[mi][ni][q] = 0.0f;

    const int lrow = lane & 15;
    const int lcol = (lane >> 4) << 3;

    for (int kt = 0; kt < D; kt += 32) {
        __syncthreads();
#pragma unroll
        for (int l = 0; l < 2; l++) {
            int idx = t + l * 256;
            int r = idx >> 2, c = idx & 3;
            const size_t g = (size_t)(m0 + r) * D + kt + c * 8;
            *(float4*)&sAh[r][c * 8] = *(const float4*)(Ah + g);
            *(float4*)&sAl[r][c * 8] = *(const float4*)(Al + g);
        }
        {
            int r = t >> 2, c = t & 3;
            const size_t g = (size_t)(n0 + r) * D + kt + c * 8;
            *(float4*)&sBh[r][c * 8] = *(const float4*)(Bh + g);
            *(float4*)&sBl[r][c * 8] = *(const float4*)(Bl + g);
        }
        __syncthreads();

#pragma unroll
        for (int ks = 0; ks < 2; ks++) {
            const int kc = ks * 16 + lcol;
            uint32_t ah[2][4], al[2][4], bh[4][2], bl[4][2];
#pragma unroll
            for (int mi = 0; mi < 2; mi++) {
                int r = warp_m * 32 + mi * 16 + lrow;
                ldmx4(ah[mi], uAh + (uint32_t)(r * GPAD + kc) * 2);
                ldmx4(al[mi], uAl + (uint32_t)(r * GPAD + kc) * 2);
            }
#pragma unroll
            for (int np = 0; np < 2; np++) {
                int r = warp_n * 32 + np * 16 + lrow;
                uint32_t tmp[4];
                ldmx4(tmp, uBh + (uint32_t)(r * GPAD + kc) * 2);
                bh[np * 2 + 0][0] = tmp[0]; bh[np * 2 + 0][1] = tmp[2];
                bh[np * 2 + 1][0] = tmp[1]; bh[np * 2 + 1][1] = tmp[3];
                ldmx4(tmp, uBl + (uint32_t)(r * GPAD + kc) * 2);
                bl[np * 2 + 0][0] = tmp[0]; bl[np * 2 + 0][1] = tmp[2];
                bl[np * 2 + 1][0] = tmp[1]; bl[np * 2 + 1][1] = tmp[3];
            }
#pragma unroll
            for (int mi = 0; mi < 2; mi++)
#pragma unroll
                for (int ni = 0; ni < 4; ni++) {
                    mma_bf16(acc[mi][ni], ah[mi], bh[ni]);
                    mma_bf16(acc[mi][ni], al[mi], bh[ni]);
                    mma_bf16(acc[mi][ni], ah[mi], bl[ni]);
                }
        }
    }

    const int rb = m0 + warp_m * 32 + (lane >> 2);
    const int cb = n0 + warp_n * 32 + (lane & 3) * 2;
#pragma unroll
    for (int mi = 0; mi < 2; mi++)
#pragma unroll
        for (int ni = 0; ni < 4; ni++) {
            int r = rb + mi * 16;
            int c = cb + ni * 8;
            float2 v0, v1;
            v0.x = acc[mi][ni][0] + bias[c];
            v0.y = acc[mi][ni][1] + bias[c + 1];
            v1.x = acc[mi][ni][2] + bias[c];
            v1.y = acc[mi][ni][3] + bias[c + 1];
            *(float2*)(C + (size_t)r * D + c) = v0;
            *(float2*)(C + (size_t)(r + 8) * D + c) = v1;
        }
}

// ============================================================
// Flash attention via mma.sync, bf16x3 (causal).
// Grid: (16 q-tiles reversed, 48 bh). Block 256 = 8 warps.
// Q tile 128 rows (warp = 16 rows), KV tile 64. dk = 64.
// Output written directly as split bf16 hi/lo.
// ============================================================
#define APITCH 72     // bf16 per smem row (64 data + 8 pad) = 144 B
#define SM_QH 0
#define SM_QL (128 * APITCH)
#define SM_KH (2 * 128 * APITCH)
#define SM_KL (SM_KH + 64 * APITCH)
#define SM_VH (SM_KL + 64 * APITCH)
#define SM_VL (SM_VH + 64 * APITCH)
#define SMEM_FA ((SM_VL + 64 * APITCH) * 2)   // bytes = 73728

__global__ __launch_bounds__(256) void flash_attn_mma(
    const __nv_bfloat16* __restrict__ qh, const __nv_bfloat16* __restrict__ ql,
    const __nv_bfloat16* __restrict__ kh, const __nv_bfloat16* __restrict__ kl,
    const __nv_bfloat16* __restrict__ vth, const __nv_bfloat16* __restrict__ vtl,
    __nv_bfloat16* __restrict__ oh, __nv_bfloat16* __restrict__ ol)
{
    extern __shared__ __nv_bfloat16 sm[];
    const int t = threadIdx.x, lane = t & 31, w = t >> 5;
    const int qb = gridDim.x - 1 - blockIdx.x;    // longest first
    const int bh = blockIdx.y;
    const int bb = bh / H, hh = bh % H;

    const uint32_t uQh = smem_u32(sm + SM_QH);
    const uint32_t uQl = smem_u32(sm + SM_QL);
    const uint32_t uKh = smem_u32(sm + SM_KH);
    const uint32_t uKl = smem_u32(sm + SM_KL);
    const uint32_t uVh = smem_u32(sm + SM_VH);
    const uint32_t uVl = smem_u32(sm + SM_VL);

    const size_t qrow0 = (size_t)bb * S + qb * 128;

    // ---- load Q tile (both halves): 128 rows x 8 chunks ----
#pragma unroll
    for (int l = 0; l < 4; l++) {
        int idx = t + l * 256;
        int r = idx >> 3, c8 = (idx & 7) << 3;
        size_t g = (qrow0 + r) * D + hh * 64 + c8;
        *(float4*)(sm + SM_QH + r * APITCH + c8) = *(const float4*)(qh + g);
        *(float4*)(sm + SM_QL + r * APITCH + c8) = *(const float4*)(ql + g);
    }
    __syncthreads();

    // hoist Q fragments (A-operand, 16x16 per kf)
    uint32_t qfh[4][4], qfl[4][4];
    {
        const int arow = w * 16 + (lane & 15);
        const int acol_off = (lane >> 4) << 3;
#pragma unroll
        for (int kf = 0; kf < 4; kf++) {
            uint32_t off = (uint32_t)(arow * APITCH + kf * 16 + acol_off) * 2;
            ldmx4(qfh[kf], uQh + off);
            ldmx4(qfl[kf], uQl + off);
        }
    }

    float m_i[2] = {-INFINITY, -INFINITY};
    float l_i[2] = {0.0f, 0.0f};
    float o[8][4];
#pragma unroll
    for (int nf = 0; nf < 8; nf++)
#pragma unroll
        for (int q = 0; q < 4; q++) o[nf][q] = 0.0f;

    const int brow_off = lane & 7;
    const int bcol_off = lane & 8;
    const int kt_end = 2 * qb + 1;

    for (int kt = 0; kt <= kt_end; kt++) {
        __syncthreads();
        // load K and Vt tiles (hi+lo): 64 rows x 8 chunks each
#pragma unroll
        for (int l = 0; l < 2; l++) {
            int idx = t + l * 256;
            int r = idx >> 3, c8 = (idx & 7) << 3;
            size_t gk = ((size_t)bb * S + kt * 64 + r) * D + hh * 64 + c8;
            *(float4*)(sm + SM_KH + r * APITCH + c8) = *(const float4*)(kh + gk);
            *(float4*)(sm + SM_KL + r * APITCH + c8) = *(const float4*)(kl + gk);
            size_t gv = ((size_t)bh * 64 + r) * S + kt * 64 + c8;
            *(float4*)(sm + SM_VH + r * APITCH + c8) = *(const float4*)(vth + gv);
            *(float4*)(sm + SM_VL + r * APITCH + c8) = *(const float4*)(vtl + gv);
        }
        __syncthreads();

        // ---- S = Q K^T (3-term split) ----
        float s[8][4];
#pragma unroll
        for (int nf = 0; nf < 8; nf++) {
#pragma unroll
            for (int q = 0; q < 4; q++) s[nf][q] = 0.0f;
#pragma unroll
            for (int kf = 0; kf < 4; kf++) {
                uint32_t bhf[2], blf[2];
                uint32_t off = (uint32_t)((nf * 8 + brow_off) * APITCH +
                                          kf * 16 + bcol_off) * 2;
                ldmx2(bhf, uKh + off);
                ldmx2(blf, uKl + off);
                mma_bf16(s[nf], qfh[kf], bhf);
                mma_bf16(s[nf], qfl[kf], bhf);
                mma_bf16(s[nf], qfh[kf], blf);
            }
        }

        // ---- causal mask (only last two tiles) ----
        if (kt >= 2 * qb) {
            const int row0 = qb * 128 + w * 16 + (lane >> 2);
#pragma unroll
            for (int nf = 0; nf < 8; nf++) {
                int col = kt * 64 + nf * 8 + 2 * (lane & 3);
                if (col > row0)     s[nf][0] = -1e30f;
                if (col + 1 > row0) s[nf][1] = -1e30f;
                if (col > row0 + 8)     s[nf][2] = -1e30f;
                if (col + 1 > row0 + 8) s[nf][3] = -1e30f;
            }
        }

        // ---- online softmax (two row-halves per thread) ----
#pragma unroll
        for (int hlf = 0; hlf < 2; hlf++) {
            float mx = -INFINITY;
#pragma unroll
            for (int nf = 0; nf < 8; nf++) {
                mx = fmaxf(mx, s[nf][2 * hlf]);
                mx = fmaxf(mx, s[nf][2 * hlf + 1]);
            }
            mx = fmaxf(mx, __shfl_xor_sync(0xffffffffu, mx, 1));
            mx = fmaxf(mx, __shfl_xor_sync(0xffffffffu, mx, 2));

            float mnew = fmaxf(m_i[hlf], mx);
            float f = __expf(m_i[hlf] - mnew);
            m_i[hlf] = mnew;

            float rs = 0.0f;
#pragma unroll
            for (int nf = 0; nf < 8; nf++) {
                float p0 = __expf(s[nf][2 * hlf] - mnew);
                float p1 = __expf(s[nf][2 * hlf + 1] - mnew);
                s[nf][2 * hlf] = p0; s[nf][2 * hlf + 1] = p1;
                rs += p0 + p1;
            }
            rs += __shfl_xor_sync(0xffffffffu, rs, 1);
            rs += __shfl_xor_sync(0xffffffffu, rs, 2);

            l_i[hlf] = l_i[hlf] * f + rs;
#pragma unroll
            for (int nf = 0; nf < 8; nf++) {
                o[nf][2 * hlf] *= f;
                o[nf][2 * hlf + 1] *= f;
            }
        }

        // ---- pack P into A-fragments (hi + lo) ----
        uint32_t ph[4][4], pl[4][4];
#pragma unroll
        for (int g = 0; g < 4; g++) {
            split_pack(s[2 * g][0], s[2 * g][1], ph[g][0], pl[g][0]);
            split_pack(s[2 * g][2], s[2 * g][3], ph[g][1], pl[g][1]);
            split_pack(s[2 * g + 1][0], s[2 * g + 1][1], ph[g][2], pl[g][2]);
            split_pack(s[2 * g + 1][2], s[2 * g + 1][3], ph[g][3], pl[g][3]);
        }

        // ---- O += P V (3-term split) ----
#pragma unroll
        for (int nf = 0; nf < 8; nf++) {
#pragma unroll
            for (int g = 0; g < 4; g++) {
                uint32_t bvh[2], bvl[2];
                uint32_t off = (uint32_t)((nf * 8 + brow_off) * APITCH +
                                          g * 16 + bcol_off) * 2;
                ldmx2(bvh, uVh + off);
                ldmx2(bvl, uVl + off);
                mma_bf16(o[nf], ph[g], bvh);
                mma_bf16(o[nf], pl[g], bvh);
                mma_bf16(o[nf], ph[g], bvl);
            }
        }
    }

    // ---- finalize: /l, split-write to oh/ol ----
    const float inv0 = 1.0f / l_i[0];
    const float inv1 = 1.0f / l_i[1];
    const size_t r0g = qrow0 + w * 16 + (lane >> 2);
    const int cb = hh * 64 + 2 * (lane & 3);
#pragma unroll
    for (int nf = 0; nf < 8; nf++) {
        uint32_t h, lo;
        split_pack(o[nf][0] * inv0, o[nf][1] * inv0, h, lo);
        *(uint32_t*)(oh + r0g * D + cb + nf * 8) = h;
        *(uint32_t*)(ol + r0g * D + cb + nf * 8) = lo;
        split_pack(o[nf][2] * inv1, o[nf][3] * inv1, h, lo);
        *(uint32_t*)(oh + (r0g + 8) * D + cb + nf * 8) = h;
        *(uint32_t*)(ol + (r0g + 8) * D + cb + nf * 8) = lo;
    }
}

// ============================================================
extern "C" void kernel_launch(void* const* d_in, const int* in_sizes, int n_in,
                              void* d_out, int out_size)
{
    const float* x   = (const float*)d_in[0];
    const float* w_q = (const float*)d_in[1];
    const float* b_q = (const float*)d_in[2];
    const float* w_k = (const float*)d_in[3];
    const float* b_k = (const float*)d_in[4];
    const float* w_v = (const float*)d_in[5];
    const float* b_v = (const float*)d_in[6];
    const float* w_o = (const float*)d_in[7];
    const float* b_o = (const float*)d_in[8];

    float *Qb, *Kb, *Vb;
    __nv_bfloat16 *xh, *xl, *oh, *ol, *wh, *wl;
    __nv_bfloat16 *qh, *ql, *kh, *kl, *vth, *vtl;
    cudaGetSymbolAddress((void**)&Qb, g_Q);
    cudaGetSymbolAddress((void**)&Kb, g_K);
    cudaGetSymbolAddress((void**)&Vb, g_V);
    cudaGetSymbolAddress((void**)&xh, g_xh);
    cudaGetSymbolAddress((void**)&xl, g_xl);
    cudaGetSymbolAddress((void**)&oh, g_oh);
    cudaGetSymbolAddress((void**)&ol, g_ol);
    cudaGetSymbolAddress((void**)&wh, g_wh);
    cudaGetSymbolAddress((void**)&wl, g_wl);
    cudaGetSymbolAddress((void**)&qh, g_qh);
    cudaGetSymbolAddress((void**)&ql, g_ql);
    cudaGetSymbolAddress((void**)&kh, g_kh);
    cudaGetSymbolAddress((void**)&kl, g_kl);
    cudaGetSymbolAddress((void**)&vth, g_vth);
    cudaGetSymbolAddress((void**)&vtl, g_vtl);

    cudaFuncSetAttribute(flash_attn_mma,
        cudaFuncAttributeMaxDynamicSharedMemorySize, SMEM_FA);

    const int n4 = M_ROWS * D / 4;
    const int w4 = D * D / 4;

    // input + weight splits
    convert_split<<<(n4 + 255) / 256, 256>>>(
        (const float4*)x, (__nv_bfloat162*)xh, (__nv_bfloat162*)xl, n4, 1.0f);
    {
        const float* ws[4] = {w_q, w_k, w_v, w_o};
        for (int i = 0; i < 4; i++)
            convert_split<<<(w4 + 255) / 256, 256>>>(
                (const float4*)ws[i],
                (__nv_bfloat162*)(wh + (size_t)i * D * D),
                (__nv_bfloat162*)(wl + (size_t)i * D * D), w4, 1.0f);
    }

    dim3 ggrid(D / 64, M_ROWS / 128);   // (12, 64)
    gemm_mma<<<ggrid, 256>>>(xh, xl, wh + 0 * (size_t)D * D,
                             wl + 0 * (size_t)D * D, b_q, Qb);
    gemm_mma<<<ggrid, 256>>>(xh, xl, wh + 1 * (size_t)D * D,
                             wl + 1 * (size_t)D * D, b_k, Kb);
    gemm_mma<<<ggrid, 256>>>(xh, xl, wh + 2 * (size_t)D * D,
                             wl + 2 * (size_t)D * D, b_v, Vb);

    // attention-operand preparation
    convert_split<<<(n4 + 255) / 256, 256>>>(
        (const float4*)Qb, (__nv_bfloat162*)qh, (__nv_bfloat162*)ql, n4, SCALE);
    convert_split<<<(n4 + 255) / 256, 256>>>(
        (const float4*)Kb, (__nv_bfloat162*)kh, (__nv_bfloat162*)kl, n4, 1.0f);
    transpose_split_v<<<dim3(S / 64, B * H), 256>>>(Vb, vth, vtl);

    flash_attn_mma<<<dim3(S / 128, B * H), 256, SMEM_FA>>>(
        qh, ql, kh, kl, vth, vtl, oh, ol);

    gemm_mma<<<ggrid, 256>>>(oh, ol, wh + 3 * (size_t)D * D,
                             wl + 3 * (size_t)D * D, b_o, (float*)d_out);
}

// round 17
// speedup vs baseline: 3.1230x; 1.1830x over previous
#include <cuda_runtime.h>
#include <cuda_bf16.h>
#include <cuda_fp16.h>
#include <math.h>
#include <stdint.h>

// Problem constants
#define B 4
#define S 2048
#define D 768
#define H 12
#define DK 64
#define M_ROWS (B * S)       // 8192
#define SCALE 0.125f         // 1/sqrt(64)

// -------- scratch (no allocations allowed) --------
__device__ float g_V[M_ROWS * D];
__device__ __nv_bfloat16 g_xh[M_ROWS * D];
__device__ __nv_bfloat16 g_xl[M_ROWS * D];
__device__ __nv_bfloat16 g_oh[M_ROWS * D];
__device__ __nv_bfloat16 g_ol[M_ROWS * D];
__device__ __nv_bfloat16 g_wh[4 * D * D];
__device__ __nv_bfloat16 g_wl[4 * D * D];
__device__ __half g_qh[M_ROWS * D];
__device__ __half g_ql[M_ROWS * D];
__device__ __half g_kh[M_ROWS * D];
__device__ __half g_kl[M_ROWS * D];     // dummy sink for K lo
__device__ __half g_vth[B * H * DK * S];

__device__ __forceinline__ uint32_t smem_u32(const void* p) {
    uint32_t a;
    asm("{ .reg .u64 t; cvta.to.shared.u64 t, %1; cvt.u32.u64 %0, t; }"
        : "=r"(a) : "l"(p));
    return a;
}

__device__ __forceinline__ void ldmx4(uint32_t* r, uint32_t addr) {
    asm volatile("ldmatrix.sync.aligned.m8n8.x4.shared.b16 {%0,%1,%2,%3}, [%4];"
        : "=r"(r[0]), "=r"(r[1]), "=r"(r[2]), "=r"(r[3]) : "r"(addr));
}
__device__ __forceinline__ void ldmx2(uint32_t* r, uint32_t addr) {
    asm volatile("ldmatrix.sync.aligned.m8n8.x2.shared.b16 {%0,%1}, [%2];"
        : "=r"(r[0]), "=r"(r[1]) : "r"(addr));
}
__device__ __forceinline__ void mma_bf16(float* c,
    const uint32_t* a, const uint32_t* b)
{
    asm volatile(
        "mma.sync.aligned.m16n8k16.row.col.f32.bf16.bf16.f32 "
        "{%0,%1,%2,%3}, {%4,%5,%6,%7}, {%8,%9}, {%0,%1,%2,%3};"
        : "+f"(c[0]), "+f"(c[1]), "+f"(c[2]), "+f"(c[3])
        : "r"(a[0]), "r"(a[1]), "r"(a[2]), "r"(a[3]), "r"(b[0]), "r"(b[1]));
}
__device__ __forceinline__ void mma_f16(float* c,
    const uint32_t* a, const uint32_t* b)
{
    asm volatile(
        "mma.sync.aligned.m16n8k16.row.col.f32.f16.f16.f32 "
        "{%0,%1,%2,%3}, {%4,%5,%6,%7}, {%8,%9}, {%0,%1,%2,%3};"
        : "+f"(c[0]), "+f"(c[1]), "+f"(c[2]), "+f"(c[3])
        : "r"(a[0]), "r"(a[1]), "r"(a[2]), "r"(a[3]), "r"(b[0]), "r"(b[1]));
}

__device__ __forceinline__ void split_pack(float a, float b,
                                           uint32_t& hi, uint32_t& lo)
{
    __nv_bfloat16 ha = __float2bfloat16(a), hb = __float2bfloat16(b);
    __nv_bfloat162 Hv, Lv;
    Hv.x = ha; Hv.y = hb;
    Lv.x = __float2bfloat16(a - __bfloat162float(ha));
    Lv.y = __float2bfloat16(b - __bfloat162float(hb));
    hi = *(uint32_t*)&Hv; lo = *(uint32_t*)&Lv;
}

__device__ __forceinline__ void split_pack_h(float a, float b,
                                             uint32_t& hi, uint32_t& lo)
{
    __half ha = __float2half_rn(a), hb = __float2half_rn(b);
    __half2 Hv, Lv;
    Hv.x = ha; Hv.y = hb;
    Lv.x = __float2half_rn(a - __half2float(ha));
    Lv.y = __float2half_rn(b - __half2float(hb));
    hi = *(uint32_t*)&Hv; lo = *(uint32_t*)&Lv;
}

// ============================================================
// Split conversion: fp32 -> (bf16 hi, bf16 lo)
// ============================================================
__global__ void convert_split(const float4* __restrict__ in,
                              __nv_bfloat162* __restrict__ hi,
                              __nv_bfloat162* __restrict__ lo, int n4)
{
    int i = blockIdx.x * blockDim.x + threadIdx.x;
    if (i >= n4) return;
    float4 v = in[i];
    uint32_t h0, l0, h1, l1;
    split_pack(v.x, v.y, h0, l0);
    split_pack(v.z, v.w, h1, l1);
    ((uint32_t*)hi)[2 * i] = h0; ((uint32_t*)hi)[2 * i + 1] = h1;
    ((uint32_t*)lo)[2 * i] = l0; ((uint32_t*)lo)[2 * i + 1] = l1;
}

// ============================================================
// V transpose: g_V [b*S][768] fp32 -> g_vth [bh][dk=64][S] fp16
// ============================================================
__global__ __launch_bounds__(256) void transpose_v_h(
    const float* __restrict__ V, __half* __restrict__ vth)
{
    __shared__ float tile[64][65];
    const int sblk = blockIdx.x;
    const int bh = blockIdx.y;
    const int bb = bh / H, hh = bh % H;
    const int t = threadIdx.x;

#pragma unroll
    for (int l = 0; l < 4; l++) {
        int idx = t + l * 256;
        int r = idx >> 4, c4 = (idx & 15) << 2;
        float4 v = *(const float4*)(V +
            ((size_t)bb * S + sblk * 64 + r) * D + hh * 64 + c4);
        tile[r][c4 + 0] = v.x; tile[r][c4 + 1] = v.y;
        tile[r][c4 + 2] = v.z; tile[r][c4 + 3] = v.w;
    }
    __syncthreads();

#pragma unroll
    for (int l = 0; l < 8; l++) {
        int p = t + l * 256;
        int c = p >> 5;              // dk
        int sp = p & 31;             // seq pair
        __half2 hv;
        hv.x = __float2half_rn(tile[2 * sp][c]);
        hv.y = __float2half_rn(tile[2 * sp + 1][c]);
        size_t addr = ((size_t)bh * 64 + c) * S + sblk * 64 + 2 * sp;
        *(uint32_t*)(vth + addr) = *(uint32_t*)&hv;
    }
}

// ============================================================
// bf16x3 GEMM via mma.sync. Optional fused epilogue:
// if Oh != nullptr, write (acc+bias)*oscale as fp16 hi/lo split
// instead of fp32.
// ============================================================
#define GPAD 40

__global__ __launch_bounds__(256) void gemm_mma(
    const __nv_bfloat16* __restrict__ Ah, const __nv_bfloat16* __restrict__ Al,
    const __nv_bfloat16* __restrict__ Bh, const __nv_bfloat16* __restrict__ Bl,
    const float* __restrict__ bias, float* __restrict__ C,
    __half* __restrict__ Oh, __half* __restrict__ Ol, float oscale)
{
    __shared__ __nv_bfloat16 sAh[128][GPAD];
    __shared__ __nv_bfloat16 sAl[128][GPAD];
    __shared__ __nv_bfloat16 sBh[64][GPAD];
    __shared__ __nv_bfloat16 sBl[64][GPAD];

    const int t = threadIdx.x;
    const int lane = t & 31;
    const int wid = t >> 5;
    const int warp_m = wid & 3;
    const int warp_n = wid >> 2;
    const int m0 = blockIdx.y * 128;
    const int n0 = blockIdx.x * 64;

    const uint32_t uAh = smem_u32(&sAh[0][0]);
    const uint32_t uAl = smem_u32(&sAl[0][0]);
    const uint32_t uBh = smem_u32(&sBh[0][0]);
    const uint32_t uBl = smem_u32(&sBl[0][0]);

    float acc[2][4][4];
#pragma unroll
    for (int mi = 0; mi < 2; mi++)
#pragma unroll
        for (int ni = 0; ni < 4; ni++)
#pragma unroll
            for (int q = 0; q < 4; q++) acc[mi][ni][q] = 0.0f;

    const int lrow = lane & 15;
    const int lcol = (lane >> 4) << 3;

    for (int kt = 0; kt < D; kt += 32) {
        __syncthreads();
#pragma unroll
        for (int l = 0; l < 2; l++) {
            int idx = t + l * 256;
            int r = idx >> 2, c = idx & 3;
            const size_t g = (size_t)(m0 + r) * D + kt + c * 8;
            *(float4*)&sAh[r][c * 8] = *(const float4*)(Ah + g);
            *(float4*)&sAl[r][c * 8] = *(const float4*)(Al + g);
        }
        {
            int r = t >> 2, c = t & 3;
            const size_t g = (size_t)(n0 + r) * D + kt + c * 8;
            *(float4*)&sBh[r][c * 8] = *(const float4*)(Bh + g);
            *(float4*)&sBl[r][c * 8] = *(const float4*)(Bl + g);
        }
        __syncthreads();

#pragma unroll
        for (int ks = 0; ks < 2; ks++) {
            const int kc = ks * 16 + lcol;
            uint32_t ah[2][4], al[2][4], bh[4][2], bl[4][2];
#pragma unroll
            for (int mi = 0; mi < 2; mi++) {
                int r = warp_m * 32 + mi * 16 + lrow;
                ldmx4(ah[mi], uAh + (uint32_t)(r * GPAD + kc) * 2);
                ldmx4(al[mi], uAl + (uint32_t)(r * GPAD + kc) * 2);
            }
#pragma unroll
            for (int np = 0; np < 2; np++) {
                int r = warp_n * 32 + np * 16 + lrow;
                uint32_t tmp[4];
                ldmx4(tmp, uBh + (uint32_t)(r * GPAD + kc) * 2);
                bh[np * 2 + 0][0] = tmp[0]; bh[np * 2 + 0][1] = tmp[2];
                bh[np * 2 + 1][0] = tmp[1]; bh[np * 2 + 1][1] = tmp[3];
                ldmx4(tmp, uBl + (uint32_t)(r * GPAD + kc) * 2);
                bl[np * 2 + 0][0] = tmp[0]; bl[np * 2 + 0][1] = tmp[2];
                bl[np * 2 + 1][0] = tmp[1]; bl[np * 2 + 1][1] = tmp[3];
            }
#pragma unroll
            for (int mi = 0; mi < 2; mi++)
#pragma unroll
                for (int ni = 0; ni < 4; ni++) {
                    mma_bf16(acc[mi][ni], ah[mi], bh[ni]);
                    mma_bf16(acc[mi][ni], al[mi], bh[ni]);
                    mma_bf16(acc[mi][ni], ah[mi], bl[ni]);
                }
        }
    }

    const int rb = m0 + warp_m * 32 + (lane >> 2);
    const int cb = n0 + warp_n * 32 + (lane & 3) * 2;
    if (Oh != nullptr) {
#pragma unroll
        for (int mi = 0; mi < 2; mi++)
#pragma unroll
            for (int ni = 0; ni < 4; ni++) {
                int r = rb + mi * 16;
                int c = cb + ni * 8;
                float a0 = (acc[mi][ni][0] + bias[c]) * oscale;
                float a1 = (acc[mi][ni][1] + bias[c + 1]) * oscale;
                uint32_t h, lo;
                split_pack_h(a0, a1, h, lo);
                *(uint32_t*)(Oh + (size_t)r * D + c) = h;
                *(uint32_t*)(Ol + (size_t)r * D + c) = lo;
                a0 = (acc[mi][ni][2] + bias[c]) * oscale;
                a1 = (acc[mi][ni][3] + bias[c + 1]) * oscale;
                split_pack_h(a0, a1, h, lo);
                *(uint32_t*)(Oh + (size_t)(r + 8) * D + c) = h;
                *(uint32_t*)(Ol + (size_t)(r + 8) * D + c) = lo;
            }
    } else {
#pragma unroll
        for (int mi = 0; mi < 2; mi++)
#pragma unroll
            for (int ni = 0; ni < 4; ni++) {
                int r = rb + mi * 16;
                int c = cb + ni * 8;
                float2 v0, v1;
                v0.x = acc[mi][ni][0] + bias[c];
                v0.y = acc[mi][ni][1] + bias[c + 1];
                v1.x = acc[mi][ni][2] + bias[c];
                v1.y = acc[mi][ni][3] + bias[c + 1];
                *(float2*)(C + (size_t)r * D + c) = v0;
                *(float2*)(C + (size_t)(r + 8) * D + c) = v1;
            }
    }
}

// ============================================================
// Flash attention via mma.sync, fp16 (causal).
// S = (Qh+Ql)·Kh   (Q split to 22 bits, K hi-only)
// O = (Ph+Pl)·Vh   (P split to 22 bits, V hi-only)
// Grid: (16 q-tiles reversed, 48 bh). Block 256 = 8 warps.
// Output written as split bf16 hi/lo for the final GEMM.
// ============================================================
#define APITCH 72     // fp16 per smem row (64 data + 8 pad) = 144 B
#define SM_QH 0
#define SM_QL (128 * APITCH)
#define SM_KH (2 * 128 * APITCH)
#define SM_VH (SM_KH + 64 * APITCH)
#define SMEM_FA ((SM_VH + 64 * APITCH) * 2)   // 55296 bytes

__global__ __launch_bounds__(256) void flash_attn_mma(
    const __half* __restrict__ qh, const __half* __restrict__ ql,
    const __half* __restrict__ kh, const __half* __restrict__ vth,
    __nv_bfloat16* __restrict__ oh, __nv_bfloat16* __restrict__ ol)
{
    extern __shared__ __half sm[];
    const int t = threadIdx.x, lane = t & 31, w = t >> 5;
    const int qb = gridDim.x - 1 - blockIdx.x;    // longest first
    const int bh = blockIdx.y;
    const int bb = bh / H, hh = bh % H;

    const uint32_t uQh = smem_u32(sm + SM_QH);
    const uint32_t uQl = smem_u32(sm + SM_QL);
    const uint32_t uKh = smem_u32(sm + SM_KH);
    const uint32_t uVh = smem_u32(sm + SM_VH);

    const size_t qrow0 = (size_t)bb * S + qb * 128;

    // ---- load Q tile (hi + lo): 128 rows x 8 chunks ----
#pragma unroll
    for (int l = 0; l < 4; l++) {
        int idx = t + l * 256;
        int r = idx >> 3, c8 = (idx & 7) << 3;
        size_t g = (qrow0 + r) * D + hh * 64 + c8;
        *(float4*)(sm + SM_QH + r * APITCH + c8) = *(const float4*)(qh + g);
        *(float4*)(sm + SM_QL + r * APITCH + c8) = *(const float4*)(ql + g);
    }
    __syncthreads();

    // hoist Q fragments
    uint32_t qfh[4][4], qfl[4][4];
    {
        const int arow = w * 16 + (lane & 15);
        const int acol_off = (lane >> 4) << 3;
#pragma unroll
        for (int kf = 0; kf < 4; kf++) {
            uint32_t off = (uint32_t)(arow * APITCH + kf * 16 + acol_off) * 2;
            ldmx4(qfh[kf], uQh + off);
            ldmx4(qfl[kf], uQl + off);
        }
    }

    float m_i[2] = {-INFINITY, -INFINITY};
    float l_i[2] = {0.0f, 0.0f};
    float o[8][4];
#pragma unroll
    for (int nf = 0; nf < 8; nf++)
#pragma unroll
        for (int q = 0; q < 4; q++) o[nf][q] = 0.0f;

    const int brow_off = lane & 7;
    const int bcol_off = lane & 8;
    const int kt_end = 2 * qb + 1;

    for (int kt = 0; kt <= kt_end; kt++) {
        __syncthreads();
        // load K and Vt tiles (hi only): 64 rows x 8 chunks
#pragma unroll
        for (int l = 0; l < 2; l++) {
            int idx = t + l * 256;
            int r = idx >> 3, c8 = (idx & 7) << 3;
            size_t gk = ((size_t)bb * S + kt * 64 + r) * D + hh * 64 + c8;
            *(float4*)(sm + SM_KH + r * APITCH + c8) = *(const float4*)(kh + gk);
            size_t gv = ((size_t)bh * 64 + r) * S + kt * 64 + c8;
            *(float4*)(sm + SM_VH + r * APITCH + c8) = *(const float4*)(vth + gv);
        }
        __syncthreads();

        // ---- S = (Qh + Ql) Kh^T ----
        float s[8][4];
#pragma unroll
        for (int nf = 0; nf < 8; nf++) {
#pragma unroll
            for (int q = 0; q < 4; q++) s[nf][q] = 0.0f;
#pragma unroll
            for (int kf = 0; kf < 4; kf++) {
                uint32_t bhf[2];
                uint32_t off = (uint32_t)((nf * 8 + brow_off) * APITCH +
                                          kf * 16 + bcol_off) * 2;
                ldmx2(bhf, uKh + off);
                mma_f16(s[nf], qfh[kf], bhf);
                mma_f16(s[nf], qfl[kf], bhf);
            }
        }

        // ---- causal mask (only last two tiles) ----
        if (kt >= 2 * qb) {
            const int row0 = qb * 128 + w * 16 + (lane >> 2);
#pragma unroll
            for (int nf = 0; nf < 8; nf++) {
                int col = kt * 64 + nf * 8 + 2 * (lane & 3);
                if (col > row0)     s[nf][0] = -1e30f;
                if (col + 1 > row0) s[nf][1] = -1e30f;
                if (col > row0 + 8)     s[nf][2] = -1e30f;
                if (col + 1 > row0 + 8) s[nf][3] = -1e30f;
            }
        }

        // ---- online softmax (two row-halves per thread) ----
#pragma unroll
        for (int hlf = 0; hlf < 2; hlf++) {
            float mx = -INFINITY;
#pragma unroll
            for (int nf = 0; nf < 8; nf++) {
                mx = fmaxf(mx, s[nf][2 * hlf]);
                mx = fmaxf(mx, s[nf][2 * hlf + 1]);
            }
            mx = fmaxf(mx, __shfl_xor_sync(0xffffffffu, mx, 1));
            mx = fmaxf(mx, __shfl_xor_sync(0xffffffffu, mx, 2));

            float mnew = fmaxf(m_i[hlf], mx);
            float f = __expf(m_i[hlf] - mnew);
            m_i[hlf] = mnew;

            float rs = 0.0f;
#pragma unroll
            for (int nf = 0; nf < 8; nf++) {
                float p0 = __expf(s[nf][2 * hlf] - mnew);
                float p1 = __expf(s[nf][2 * hlf + 1] - mnew);
                s[nf][2 * hlf] = p0; s[nf][2 * hlf + 1] = p1;
                rs += p0 + p1;
            }
            rs += __shfl_xor_sync(0xffffffffu, rs, 1);
            rs += __shfl_xor_sync(0xffffffffu, rs, 2);

            l_i[hlf] = l_i[hlf] * f + rs;
#pragma unroll
            for (int nf = 0; nf < 8; nf++) {
                o[nf][2 * hlf] *= f;
                o[nf][2 * hlf + 1] *= f;
            }
        }

        // ---- pack P into fp16 A-fragments (hi + lo) ----
        uint32_t ph[4][4], pl[4][4];
#pragma unroll
        for (int g = 0; g < 4; g++) {
            split_pack_h(s[2 * g][0], s[2 * g][1], ph[g][0], pl[g][0]);
            split_pack_h(s[2 * g][2], s[2 * g][3], ph[g][1], pl[g][1]);
            split_pack_h(s[2 * g + 1][0], s[2 * g + 1][1], ph[g][2], pl[g][2]);
            split_pack_h(s[2 * g + 1][2], s[2 * g + 1][3], ph[g][3], pl[g][3]);
        }

        // ---- O += (Ph + Pl) Vh ----
#pragma unroll
        for (int nf = 0; nf < 8; nf++) {
#pragma unroll
            for (int g = 0; g < 4; g++) {
                uint32_t bvh[2];
                uint32_t off = (uint32_t)((nf * 8 + brow_off) * APITCH +
                                          g * 16 + bcol_off) * 2;
                ldmx2(bvh, uVh + off);
                mma_f16(o[nf], ph[g], bvh);
                mma_f16(o[nf], pl[g], bvh);
            }
        }
    }

    // ---- finalize: /l, split-write bf16 to oh/ol ----
    const float inv0 = 1.0f / l_i[0];
    const float inv1 = 1.0f / l_i[1];
    const size_t r0g = qrow0 + w * 16 + (lane >> 2);
    const int cb = hh * 64 + 2 * (lane & 3);
#pragma unroll
    for (int nf = 0; nf < 8; nf++) {
        uint32_t h, lo;
        split_pack(o[nf][0] * inv0, o[nf][1] * inv0, h, lo);
        *(uint32_t*)(oh + r0g * D + cb + nf * 8) = h;
        *(uint32_t*)(ol + r0g * D + cb + nf * 8) = lo;
        split_pack(o[nf][2] * inv1, o[nf][3] * inv1, h, lo);
        *(uint32_t*)(oh + (r0g + 8) * D + cb + nf * 8) = h;
        *(uint32_t*)(ol + (r0g + 8) * D + cb + nf * 8) = lo;
    }
}

// ============================================================
extern "C" void kernel_launch(void* const* d_in, const int* in_sizes, int n_in,
                              void* d_out, int out_size)
{
    const float* x   = (const float*)d_in[0];
    const float* w_q = (const float*)d_in[1];
    const float* b_q = (const float*)d_in[2];
    const float* w_k = (const float*)d_in[3];
    const float* b_k = (const float*)d_in[4];
    const float* w_v = (const float*)d_in[5];
    const float* b_v = (const float*)d_in[6];
    const float* w_o = (const float*)d_in[7];
    const float* b_o = (const float*)d_in[8];

    float* Vb;
    __nv_bfloat16 *xh, *xl, *oh, *ol, *wh, *wl;
    __half *qh, *ql, *kh, *kl, *vth;
    cudaGetSymbolAddress((void**)&Vb, g_V);
    cudaGetSymbolAddress((void**)&xh, g_xh);
    cudaGetSymbolAddress((void**)&xl, g_xl);
    cudaGetSymbolAddress((void**)&oh, g_oh);
    cudaGetSymbolAddress((void**)&ol, g_ol);
    cudaGetSymbolAddress((void**)&wh, g_wh);
    cudaGetSymbolAddress((void**)&wl, g_wl);
    cudaGetSymbolAddress((void**)&qh, g_qh);
    cudaGetSymbolAddress((void**)&ql, g_ql);
    cudaGetSymbolAddress((void**)&kh, g_kh);
    cudaGetSymbolAddress((void**)&kl, g_kl);
    cudaGetSymbolAddress((void**)&vth, g_vth);

    cudaFuncSetAttribute(flash_attn_mma,
        cudaFuncAttributeMaxDynamicSharedMemorySize, SMEM_FA);

    const int n4 = M_ROWS * D / 4;
    const int w4 = D * D / 4;

    // input + weight splits (bf16, for the GEMMs)
    convert_split<<<(n4 + 255) / 256, 256>>>(
        (const float4*)x, (__nv_bfloat162*)xh, (__nv_bfloat162*)xl, n4);
    {
        const float* ws[4] = {w_q, w_k, w_v, w_o};
        for (int i = 0; i < 4; i++)
            convert_split<<<(w4 + 255) / 256, 256>>>(
                (const float4*)ws[i],
                (__nv_bfloat162*)(wh + (size_t)i * D * D),
                (__nv_bfloat162*)(wl + (size_t)i * D * D), w4);
    }

    dim3 ggrid(D / 64, M_ROWS / 128);   // (12, 64)
    // Q: fused fp16-split epilogue with SCALE folded in
    gemm_mma<<<ggrid, 256>>>(xh, xl, wh + 0 * (size_t)D * D,
                             wl + 0 * (size_t)D * D, b_q,
                             nullptr, qh, ql, SCALE);
    // K: fused fp16-split epilogue (lo goes to a sink; only hi used)
    gemm_mma<<<ggrid, 256>>>(xh, xl, wh + 1 * (size_t)D * D,
                             wl + 1 * (size_t)D * D, b_k,
                             nullptr, kh, kl, 1.0f);
    // V: fp32 (transposed+converted next)
    gemm_mma<<<ggrid, 256>>>(xh, xl, wh + 2 * (size_t)D * D,
                             wl + 2 * (size_t)D * D, b_v,
                             Vb, nullptr, nullptr, 1.0f);

    transpose_v_h<<<dim3(S / 64, B * H), 256>>>(Vb, vth);

    flash_attn_mma<<<dim3(S / 128, B * H), 256, SMEM_FA>>>(
        qh, ql, kh, vth, oh, ol);

    gemm_mma<<<ggrid, 256>>>(oh, ol, wh + 3 * (size_t)D * D,
                             wl + 3 * (size_t)D * D, b_o,
                             (float*)d_out, nullptr, nullptr, 1.0f);
}